// round 16
// baseline (speedup 1.0000x reference)
#include <cuda_runtime.h>
#include <cuda_bf16.h>
#include <cstdint>
#include <cstddef>

#define BB 32
#define N1 2048
#define S1 512
#define S2 256
#define NS 32
#define R2C 0.25f
#define NSLOT 32
#define CMAX 256
#define NT1 (BB*S1*NS)
#define NT2 (BB*S2*NS)
#define POOLE 67108864ull

// ---------------- static device buffers ----------------
__device__ float g_F0[(size_t)BB*64*N1];
__device__ float g_F1t[(size_t)BB*N1*64];
__device__ float g_nx1[(size_t)BB*S1*3];
__device__ int   g_fps1[BB*S1];
__device__ int   g_gi1[(size_t)BB*S1*NS];
__device__ float g_F1max[(size_t)BB*S1*128];
__device__ float g_nx2[(size_t)BB*S2*3];
__device__ int   g_fps2[BB*S2];
__device__ int   g_gi2[(size_t)BB*S2*NS];
__device__ float g_F2max[(size_t)BB*S2*256];

__device__ __nv_bfloat16 g_Ah[POOLE];
__device__ __nv_bfloat16 g_Al[POOLE];
__device__ float g_G[POOLE];
__device__ __nv_bfloat16 g_Wh[163840];
__device__ __nv_bfloat16 g_Wl[163840];

__device__ double g_psum[6*NSLOT*CMAX];
__device__ double g_psq [6*NSLOT*CMAX];
__device__ float  g_scale[6*CMAX];
__device__ float  g_bias [6*CMAX];
__device__ int    g_ctr[8];

// ---------------- helpers ----------------
__device__ __forceinline__ void mma16816(float* c, const uint32_t* a, uint32_t b0, uint32_t b1) {
    asm volatile("mma.sync.aligned.m16n8k16.row.col.f32.bf16.bf16.f32 "
        "{%0,%1,%2,%3}, {%4,%5,%6,%7}, {%8,%9}, {%0,%1,%2,%3};"
        : "+f"(c[0]), "+f"(c[1]), "+f"(c[2]), "+f"(c[3])
        : "r"(a[0]), "r"(a[1]), "r"(a[2]), "r"(a[3]), "r"(b0), "r"(b1));
}

#define LDSMX4(r, addr) \
    asm volatile("ldmatrix.sync.aligned.m8n8.x4.shared.b16 {%0,%1,%2,%3}, [%4];" \
        : "=r"((r)[0]), "=r"((r)[1]), "=r"((r)[2]), "=r"((r)[3]) : "r"(addr))

__device__ __forceinline__ void split2(float a, float b, uint32_t& hi, uint32_t& lo)
{
    __nv_bfloat162 h = __floats2bfloat162_rn(a, b);
    float2 f = __bfloat1622float2(h);
    __nv_bfloat162 l = __floats2bfloat162_rn(a - f.x, b - f.y);
    hi = *reinterpret_cast<uint32_t*>(&h);
    lo = *reinterpret_cast<uint32_t*>(&l);
}
__device__ __forceinline__ void split4(float v0, float v1, float v2, float v3,
                                       uint2& hi, uint2& lo)
{
    split2(v0, v1, hi.x, lo.x);
    split2(v2, v3, hi.y, lo.y);
}

__device__ __forceinline__ void bn_finalize(const double* psum, const double* psq,
                                            float* sc, float* bi, int t, double invM)
{
    double s = 0.0, q = 0.0;
    for (int k = 0; k < NSLOT; k++) {
        s += __ldcg(&psum[k*CMAX + t]);
        q += __ldcg(&psq [k*CMAX + t]);
    }
    double mean = s * invM;
    double var  = q * invM - mean * mean;
    if (var < 0.0) var = 0.0;
    double sv = 1.0 / sqrt(var + 1e-5);
    sc[t] = (float)sv;
    bi[t] = (float)(-mean * sv);
}

// ---------------- dual-chain FPS (2 batches per block, lockstep syncs) ----------------
// Per-chain: 128 threads. Selection via packed key (dist_bits<<32)|(0x7fffffff-j):
// max => largest dist, ties => smallest index (matches jnp.argmax first-index).
// 3-slot rotating key avoids read/reset races across iterations.
template<int N, int S>
__device__ __forceinline__ void fps_dual(
    const float* __restrict__ Pb, int pstride, int cstride,
    int* __restrict__ outIdx, float* __restrict__ outXYZ, int b,
    float* xs, float* ys, float* zs,
    unsigned long long* keys, int ht)
{
    constexpr int PPT = N/128;
    int lane = ht & 31;
    for (int j = ht; j < N; j += 128) {
        xs[j] = Pb[(size_t)j*pstride];
        ys[j] = Pb[(size_t)j*pstride + cstride];
        zs[j] = Pb[(size_t)j*pstride + 2*cstride];
    }
    float dist[PPT];
    #pragma unroll
    for (int i = 0; i < PPT; i++) dist[i] = 1e10f;
    if (ht == 0) { keys[0] = 0ull; keys[1] = 0ull; keys[2] = 0ull; }
    __syncthreads();
    int far = 0;
    for (int s = 0; s < S; s++) {
        int p = s % 3;
        float fx = xs[far], fy = ys[far], fz = zs[far];
        if (ht == 0) {
            outIdx[(size_t)b*S + s] = far;
            float* o = &outXYZ[((size_t)b*S + s)*3];
            o[0] = fx; o[1] = fy; o[2] = fz;
            keys[(p + 1) % 3] = 0ull;
        }
        float bv = -1.f; int bi = 0x7fffffff;
        #pragma unroll
        for (int i = 0; i < PPT; i++) {
            int j = i*128 + ht;
            float dx = __fsub_rn(xs[j], fx);
            float dy = __fsub_rn(ys[j], fy);
            float dz = __fsub_rn(zs[j], fz);
            float d = __fadd_rn(__fadd_rn(__fmul_rn(dx,dx), __fmul_rn(dy,dy)), __fmul_rn(dz,dz));
            float nd = fminf(dist[i], d);
            dist[i] = nd;
            if (nd > bv) { bv = nd; bi = j; }
        }
        #pragma unroll
        for (int off = 16; off; off >>= 1) {
            float ov = __shfl_down_sync(0xffffffffu, bv, off);
            int   oi = __shfl_down_sync(0xffffffffu, bi, off);
            if (ov > bv || (ov == bv && oi < bi)) { bv = ov; bi = oi; }
        }
        if (lane == 0) {
            unsigned long long k = ((unsigned long long)__float_as_uint(bv) << 32)
                                 | (unsigned)(0x7fffffff - bi);
            atomicMax(&keys[p], k);
        }
        __syncthreads();
        unsigned long long kk = keys[p];
        far = 0x7fffffff - (int)(unsigned)(kk & 0xffffffffull);
    }
}

// ---------------- ball body (one warp per group) ----------------
__device__ __forceinline__ void ball_body(
    const float* __restrict__ Cb, int pstride, int cstride, int N,
    float qx, float qy, float qz, int* buf, int lane, int* __restrict__ giout)
{
    int cnt = 0;
    for (int base = 0; base < N && cnt < NS; base += 32) {
        int j = base + lane;
        float dx = __fsub_rn(Cb[(size_t)j*pstride], qx);
        float dy = __fsub_rn(Cb[(size_t)j*pstride + cstride], qy);
        float dz = __fsub_rn(Cb[(size_t)j*pstride + 2*cstride], qz);
        float d = __fadd_rn(__fadd_rn(__fmul_rn(dx,dx), __fmul_rn(dy,dy)), __fmul_rn(dz,dz));
        bool ok = !(d > R2C);
        unsigned m = __ballot_sync(0xffffffffu, ok);
        int pos = cnt + __popc(m & ((1u << lane) - 1u));
        if (ok && pos < NS) buf[pos] = j;
        cnt += __popc(m);
    }
    __syncwarp();
    int first = buf[0];
    int mm = cnt < NS ? cnt : NS;
    int v = (lane < mm) ? buf[lane] : first;
    giout[lane] = v;
}

// ---------------- gather body: bf16 hi/lo A, [col][CIN] K-major ----------------
template<int CH>
__device__ __forceinline__ void gather_body(
    const float* __restrict__ src, int NP,
    const float* __restrict__ sc, const float* __restrict__ bi,
    const int* __restrict__ gi, const int* __restrict__ fpsidx, int S,
    __nv_bfloat16* __restrict__ Ah, __nv_bfloat16* __restrict__ Al, int g,
    float* fc, uint32_t* fch, uint32_t* fcl, int* gix)
{
    constexpr int CIN = 2*CH;
    int t = threadIdx.x, wid = t >> 5, lane = t & 31;
    int b = g / S, s = g % S;
    if (t < 32) gix[t] = gi[(size_t)g*NS + t];
    if (t < CH) {
        int ci = fpsidx[(size_t)b*S + s];
        float v = src[((size_t)b*NP + ci)*CH + t]*sc[t] + bi[t];
        fc[t] = fmaxf(v, 0.f);
    }
    __syncthreads();
    if (t < CH/2) split2(fc[2*t], fc[2*t+1], fch[t], fcl[t]);
    __syncthreads();
    for (int k = wid; k < NS; k += 8) {
        size_t row = (size_t)b*NP + gix[k];
        size_t ob = ((size_t)g*NS + k)*CIN;
        for (int cp = lane; cp < CH/2; cp += 32) {
            int c = 2*cp;
            float2 sv = *(const float2*)&src[row*CH + c];
            float v0 = fmaxf(sv.x*sc[c]   + bi[c],   0.f);
            float v1 = fmaxf(sv.y*sc[c+1] + bi[c+1], 0.f);
            uint32_t h, l;
            split2(v0 - fc[c], v1 - fc[c+1], h, l);
            *(uint32_t*)&Ah[ob + c] = h;
            *(uint32_t*)&Al[ob + c] = l;
            *(uint32_t*)&Ah[ob + CH + c] = fch[cp];
            *(uint32_t*)&Al[ob + CH + c] = fcl[cp];
        }
    }
}

// ---------------- fused weight split fp32 -> bf16 hi/lo ----------------
__global__ void k_wsplit(const float* __restrict__ wa, const float* __restrict__ wb,
                         const float* __restrict__ wc, const float* __restrict__ wd,
                         __nv_bfloat16* __restrict__ Wh, __nv_bfloat16* __restrict__ Wl)
{
    int i = blockIdx.x*256 + threadIdx.x;
    if (i >= 163840) return;
    float v;
    if (i < 16384)      v = wa[i];
    else if (i < 32768) v = wb[i - 16384];
    else if (i < 98304) v = wc[i - 32768];
    else                v = wd[i - 98304];
    __nv_bfloat16 h = __float2bfloat16(v);
    Wh[i] = h;
    Wl[i] = __float2bfloat16(v - __bfloat162float(h));
}

// ---------------- conv1 + fps1 fused (16 dual-fps blocks FIRST) ----------------
__global__ void __launch_bounds__(256) k_conv1fps(
    const float* __restrict__ x, const float* __restrict__ W,
    float* __restrict__ F0, double* __restrict__ psum, double* __restrict__ psq,
    int* __restrict__ ctr, float* __restrict__ osc, float* __restrict__ obi,
    int* __restrict__ fps1, float* __restrict__ nx1)
{
    extern __shared__ __align__(16) char dynsm[];
    __shared__ float ws_[8], wq_[8];
    __shared__ int lastf;
    int bid = blockIdx.x, t = threadIdx.x;
    if (bid < 16) {
        int chain = t >> 7, ht = t & 127;
        int b = bid*2 + chain;
        float* base = (float*)dynsm + (size_t)chain*3*N1;
        unsigned long long* keys = (unsigned long long*)((float*)dynsm + 2*3*N1) + chain*3;
        fps_dual<N1,S1>(x + (size_t)b*3*N1, 1, N1, fps1, nx1, b,
                        base, base + N1, base + 2*N1, keys, ht);
        return;
    }
    int cb = bid - 16;
    int c = cb & 63, b = cb >> 6;
    float w0 = W[c*3], w1 = W[c*3+1], w2 = W[c*3+2];
    const float* xb = x + (size_t)b*3*N1;
    float* o = F0 + ((size_t)b*64 + c)*N1;
    float ls = 0.f, lq = 0.f;
    for (int n = t; n < N1; n += 256) {
        float v = w0*xb[n] + w1*xb[N1+n] + w2*xb[2*N1+n];
        o[n] = v; ls += v; lq += v*v;
    }
    for (int off = 16; off; off >>= 1) {
        ls += __shfl_down_sync(0xffffffffu, ls, off);
        lq += __shfl_down_sync(0xffffffffu, lq, off);
    }
    if ((t & 31) == 0) { ws_[t >> 5] = ls; wq_[t >> 5] = lq; }
    __syncthreads();
    if (t == 0) {
        float S = 0.f, Q = 0.f;
        for (int i = 0; i < 8; i++) { S += ws_[i]; Q += wq_[i]; }
        atomicAdd(&psum[(b & (NSLOT-1))*CMAX + c], (double)S);
        atomicAdd(&psq [(b & (NSLOT-1))*CMAX + c], (double)Q);
        __threadfence();
        lastf = (atomicAdd(ctr, 1) == 2048 - 1) ? 1 : 0;
    }
    __syncthreads();
    if (lastf && t < 64) bn_finalize(psum, psq, osc, obi, t, 1.0/((double)BB*N1));
}

// ---------------- conv2 + ball1 fused (ball blocks FIRST) ----------------
__global__ void __launch_bounds__(256) k_conv2ball(
    const float* __restrict__ F0, const float* __restrict__ W,
    const float* __restrict__ sc0, const float* __restrict__ bi0,
    float* __restrict__ F1t, double* __restrict__ psum, double* __restrict__ psq,
    int* __restrict__ ctr, float* __restrict__ osc, float* __restrict__ obi,
    const float* __restrict__ x, const float* __restrict__ nx1, int* __restrict__ gi1)
{
    __shared__ float in_t[64*64];
    __shared__ float ws[64*65];
    __shared__ float pspart[4*64], pqpart[4*64];
    __shared__ int lastf;
    __shared__ int bbuf[8][NS];
    int bid = blockIdx.x, t = threadIdx.x;
    if (bid < 2048) {
        int wid = t >> 5, lane = t & 31;
        int g = bid*8 + wid;
        int b = g / S1;
        const float* q = nx1 + (size_t)g*3;
        ball_body(x + (size_t)b*3*N1, 1, N1, N1, q[0], q[1], q[2],
                  bbuf[wid], lane, gi1 + (size_t)g*NS);
        return;
    }
    int cb = bid - 2048;
    int tile = cb & 31, b = cb >> 5;
    for (int i = t; i < 4096; i += 256) { int c = i >> 6, k = i & 63; ws[c*65 + k] = W[i]; }
    const float* F0b = F0 + (size_t)b*64*N1 + tile*64;
    for (int i = t; i < 4096; i += 256) {
        int k = i >> 6, nn = i & 63;
        float v = F0b[(size_t)k*N1 + nn]*sc0[k] + bi0[k];
        in_t[k*64 + nn] = fmaxf(v, 0.f);
    }
    __syncthreads();
    int c = t & 63, nq = t >> 6;
    float acc[16];
    #pragma unroll
    for (int j = 0; j < 16; j++) acc[j] = 0.f;
    for (int k = 0; k < 64; k++) {
        float wv = ws[c*65 + k];
        const float* ar = &in_t[k*64 + nq*16];
        #pragma unroll
        for (int jq = 0; jq < 4; jq++) {
            float4 a = *(const float4*)(ar + 4*jq);
            acc[4*jq+0] += wv*a.x; acc[4*jq+1] += wv*a.y;
            acc[4*jq+2] += wv*a.z; acc[4*jq+3] += wv*a.w;
        }
    }
    float lsum = 0.f, lsq = 0.f;
    #pragma unroll
    for (int j = 0; j < 16; j++) { float v = acc[j]; lsum += v; lsq += v*v; }
    pspart[nq*64 + c] = lsum; pqpart[nq*64 + c] = lsq;
    __syncthreads();
    #pragma unroll
    for (int j = 0; j < 16; j++) ws[(nq*16 + j)*65 + c] = acc[j];
    if (t < 64) {
        float s = pspart[t] + pspart[64+t] + pspart[128+t] + pspart[192+t];
        float q = pqpart[t] + pqpart[64+t] + pqpart[128+t] + pqpart[192+t];
        int slot = cb & (NSLOT-1);
        atomicAdd(&psum[slot*CMAX + t], (double)s);
        atomicAdd(&psq [slot*CMAX + t], (double)q);
    }
    __syncthreads();
    size_t nbase = (size_t)b*N1 + tile*64;
    for (int i = t; i < 4096; i += 256) {
        int n = i >> 6, cc = i & 63;
        F1t[(nbase + n)*64 + cc] = ws[n*65 + cc];
    }
    if (t == 0) {
        __threadfence();
        lastf = (atomicAdd(ctr, 1) == 1024 - 1) ? 1 : 0;
    }
    __syncthreads();
    if (lastf && t < 64) bn_finalize(psum, psq, osc, obi, t, 1.0/((double)BB*N1));
}

// ---------------- gather1 + fps2 fused (16 dual-fps blocks FIRST) ----------------
__global__ void __launch_bounds__(256) k_gather1fps2(
    const float* __restrict__ F1t, const float* __restrict__ sc, const float* __restrict__ bi,
    const int* __restrict__ gi1, const int* __restrict__ fps1,
    __nv_bfloat16* __restrict__ Ah, __nv_bfloat16* __restrict__ Al,
    const float* __restrict__ nx1, int* __restrict__ fps2, float* __restrict__ nx2)
{
    __shared__ float fpsm[2][3*S1];
    __shared__ unsigned long long keys2[2][3];
    __shared__ float fc[64]; __shared__ uint32_t fch[32], fcl[32]; __shared__ int gix[32];
    int bid = blockIdx.x, t = threadIdx.x;
    if (bid < 16) {
        int chain = t >> 7, ht = t & 127;
        int b = bid*2 + chain;
        float* base = fpsm[chain];
        fps_dual<S1,S2>(nx1 + (size_t)b*S1*3, 3, 1, fps2, nx2, b,
                        base, base + S1, base + 2*S1, keys2[chain], ht);
        return;
    }
    gather_body<64>(F1t, N1, sc, bi, gi1, fps1, S1, Ah, Al, bid - 16, fc, fch, fcl, gix);
}

// ---------------- ball2 (8 warps/block) ----------------
__global__ void __launch_bounds__(256) k_ball2(
    const float* __restrict__ nx1, const float* __restrict__ nx2, int* __restrict__ gi2)
{
    __shared__ int bbuf[8][NS];
    int wid = threadIdx.x >> 5, lane = threadIdx.x & 31;
    int g = blockIdx.x*8 + wid;
    int b = g / S2;
    const float* q = nx2 + (size_t)g*3;
    ball_body(nx1 + (size_t)b*S1*3, 3, 1, S1, q[0], q[1], q[2],
              bbuf[wid], lane, gi2 + (size_t)g*NS);
}

// ---------------- gather2 standalone ----------------
__global__ void __launch_bounds__(256) k_gather2(
    const float* __restrict__ F1max, const float* __restrict__ sc, const float* __restrict__ bi,
    const int* __restrict__ gi2, const int* __restrict__ fps2,
    __nv_bfloat16* __restrict__ Ah, __nv_bfloat16* __restrict__ Al)
{
    __shared__ float fc[128]; __shared__ uint32_t fch[64], fcl[64]; __shared__ int gix[32];
    gather_body<128>(F1max, S1, sc, bi, gi2, fps2, S2, Ah, Al, blockIdx.x, fc, fch, fcl, gix);
}

// ---------------- bf16 3-pass mma.sync GEMM (unchanged from measured-1646) ----------------
template<int K, int COUT, bool WRITE_G, bool BN, bool PRESPLIT>
__global__ void __launch_bounds__(256, 2) k_mma(
    const __nv_bfloat16* __restrict__ Wh, const __nv_bfloat16* __restrict__ Wl,
    const float* __restrict__ A32,
    const __nv_bfloat16* __restrict__ Ah, const __nv_bfloat16* __restrict__ Al,
    const float* __restrict__ bnsc, const float* __restrict__ bnbi,
    float* __restrict__ G, float* __restrict__ Fmax,
    double* __restrict__ psum, double* __restrict__ psq,
    int* __restrict__ ctr, int nctas, double invM,
    float* __restrict__ osc, float* __restrict__ obi)
{
    __shared__ __align__(16) __nv_bfloat16 Wht[128*40];
    __shared__ __align__(16) __nv_bfloat16 Wlt[128*40];
    __shared__ __align__(16) __nv_bfloat16 Aht[128*40];
    __shared__ __align__(16) __nv_bfloat16 Alt[128*40];
    __shared__ float sred[128], qred[128];
    __shared__ float scs[256], bis[256];
    __shared__ int lastf;

    int t = threadIdx.x, wid = t >> 5, lane = t & 31;
    int r4 = lane >> 2, q = lane & 3;
    int ntile = blockIdx.x, mtile = blockIdx.y;
    size_t colbase = (size_t)ntile*128;
    int mbase = mtile*128;
    int m0w = (wid & 3)*32, n0w = (wid >> 2)*64;

    for (int i = t; i < 128; i += 256) { sred[i] = 0.f; qred[i] = 0.f; }
    if (BN) for (int i = t; i < K; i += 256) { scs[i] = bnsc[i]; bis[i] = bnbi[i]; }

    float acc[2][8][4];
    #pragma unroll
    for (int im = 0; im < 2; im++)
        #pragma unroll
        for (int in_ = 0; in_ < 8; in_++)
            #pragma unroll
            for (int c = 0; c < 4; c++) acc[im][in_][c] = 0.f;

    constexpr int NCH = K/32;

    uint32_t whB = (uint32_t)__cvta_generic_to_shared(Wht);
    uint32_t wlB = (uint32_t)__cvta_generic_to_shared(Wlt);
    uint32_t ahB = (uint32_t)__cvta_generic_to_shared(Aht);
    uint32_t alB = (uint32_t)__cvta_generic_to_shared(Alt);
    uint32_t aOff = (uint32_t)(((m0w + (lane & 15))*40 + (lane >> 4)*8)*2);
    uint32_t bOff = (uint32_t)(((((lane & 7) + ((lane >> 4) << 3)) + n0w)*40 + ((lane >> 3) & 1)*8)*2);

    uint4 pa[4];
    uint4 pah[2], pal[2];
    if (PRESPLIT) {
        #pragma unroll
        for (int i = 0; i < 2; i++) {
            int idx = t + 256*i, row = idx >> 2, seg = idx & 3;
            pah[i] = *(const uint4*)(Ah + (colbase + row)*(size_t)K + seg*8);
            pal[i] = *(const uint4*)(Al + (colbase + row)*(size_t)K + seg*8);
        }
    } else {
        #pragma unroll
        for (int i = 0; i < 4; i++) {
            int idx = t + 256*i, row = idx >> 3, seg = idx & 7;
            pa[i] = *(const uint4*)(A32 + (colbase + row)*(size_t)K + seg*4);
        }
    }

    #pragma unroll 1
    for (int kc = 0; kc < NCH; kc++) {
        __syncthreads();
        if (PRESPLIT) {
            #pragma unroll
            for (int i = 0; i < 2; i++) {
                int idx = t + 256*i, row = idx >> 2, seg = idx & 3;
                *(uint4*)&Aht[row*40 + seg*8] = pah[i];
                *(uint4*)&Alt[row*40 + seg*8] = pal[i];
            }
        } else {
            #pragma unroll
            for (int i = 0; i < 4; i++) {
                int idx = t + 256*i, row = idx >> 3, seg = idx & 7;
                float4 f = *(float4*)&pa[i];
                if (BN) {
                    int kb = kc*32 + seg*4;
                    f.x = fmaxf(f.x*scs[kb]   + bis[kb],   0.f);
                    f.y = fmaxf(f.y*scs[kb+1] + bis[kb+1], 0.f);
                    f.z = fmaxf(f.z*scs[kb+2] + bis[kb+2], 0.f);
                    f.w = fmaxf(f.w*scs[kb+3] + bis[kb+3], 0.f);
                }
                uint2 hi, lo;
                split4(f.x, f.y, f.z, f.w, hi, lo);
                *(uint2*)&Aht[row*40 + seg*4] = hi;
                *(uint2*)&Alt[row*40 + seg*4] = lo;
            }
        }
        #pragma unroll
        for (int i = 0; i < 2; i++) {
            int idx = t + 256*i, row = idx >> 2, seg = idx & 3;
            *(uint4*)&Wht[row*40 + seg*8] =
                *(const uint4*)(Wh + (size_t)(mbase + row)*K + kc*32 + seg*8);
            *(uint4*)&Wlt[row*40 + seg*8] =
                *(const uint4*)(Wl + (size_t)(mbase + row)*K + kc*32 + seg*8);
        }
        __syncthreads();
        if (kc + 1 < NCH) {
            if (PRESPLIT) {
                #pragma unroll
                for (int i = 0; i < 2; i++) {
                    int idx = t + 256*i, row = idx >> 2, seg = idx & 3;
                    pah[i] = *(const uint4*)(Ah + (colbase + row)*(size_t)K + (kc+1)*32 + seg*8);
                    pal[i] = *(const uint4*)(Al + (colbase + row)*(size_t)K + (kc+1)*32 + seg*8);
                }
            } else {
                #pragma unroll
                for (int i = 0; i < 4; i++) {
                    int idx = t + 256*i, row = idx >> 3, seg = idx & 7;
                    pa[i] = *(const uint4*)(A32 + (colbase + row)*(size_t)K + (kc+1)*32 + seg*4);
                }
            }
        }
        #pragma unroll
        for (int kk = 0; kk < 2; kk++) {
            uint32_t akk = aOff + kk*32;
            uint32_t ah0[4], ah1[4], al0[4], al1[4];
            LDSMX4(ah0, whB + akk);
            LDSMX4(ah1, whB + akk + 1280);
            LDSMX4(al0, wlB + akk);
            LDSMX4(al1, wlB + akk + 1280);
            #pragma unroll
            for (int inp = 0; inp < 4; inp++) {
                uint32_t bkk = bOff + (uint32_t)((inp*16*40 + kk*16)*2);
                uint32_t bh[4], bl[4];
                LDSMX4(bh, ahB + bkk);
                LDSMX4(bl, alB + bkk);
                mma16816(acc[0][2*inp],   ah0, bh[0], bh[1]);
                mma16816(acc[1][2*inp],   ah1, bh[0], bh[1]);
                mma16816(acc[0][2*inp],   ah0, bl[0], bl[1]);
                mma16816(acc[1][2*inp],   ah1, bl[0], bl[1]);
                mma16816(acc[0][2*inp],   al0, bh[0], bh[1]);
                mma16816(acc[1][2*inp],   al1, bh[0], bh[1]);
                mma16816(acc[0][2*inp+1], ah0, bh[2], bh[3]);
                mma16816(acc[1][2*inp+1], ah1, bh[2], bh[3]);
                mma16816(acc[0][2*inp+1], ah0, bl[2], bl[3]);
                mma16816(acc[1][2*inp+1], ah1, bl[2], bl[3]);
                mma16816(acc[0][2*inp+1], al0, bh[2], bh[3]);
                mma16816(acc[1][2*inp+1], al1, bh[2], bh[3]);
            }
        }
    }

    // ---------------- epilogue ----------------
    if (WRITE_G) {
        #pragma unroll
        for (int im = 0; im < 2; im++)
            #pragma unroll
            for (int in_ = 0; in_ < 8; in_++) {
                size_t col = colbase + n0w + in_*8 + q*2;
                int mA = mbase + m0w + im*16 + r4;
                G[col*COUT + mA]       = acc[im][in_][0];
                G[(col+1)*COUT + mA]   = acc[im][in_][1];
                G[col*COUT + mA + 8]   = acc[im][in_][2];
                G[(col+1)*COUT + mA+8] = acc[im][in_][3];
            }
    }
    #pragma unroll
    for (int im = 0; im < 2; im++) {
        float sA = 0.f, sB = 0.f, qA = 0.f, qB = 0.f;
        float mxA[2] = {-3.4e38f, -3.4e38f}, mxB[2] = {-3.4e38f, -3.4e38f};
        #pragma unroll
        for (int in_ = 0; in_ < 8; in_++) {
            int gh = in_ >> 2;
            float v0 = acc[im][in_][0], v1 = acc[im][in_][1];
            float v2 = acc[im][in_][2], v3 = acc[im][in_][3];
            sA += v0 + v1; qA += v0*v0 + v1*v1;
            sB += v2 + v3; qB += v2*v2 + v3*v3;
            mxA[gh] = fmaxf(mxA[gh], fmaxf(v0, v1));
            mxB[gh] = fmaxf(mxB[gh], fmaxf(v2, v3));
        }
        #pragma unroll
        for (int off = 1; off <= 2; off <<= 1) {
            sA += __shfl_xor_sync(0xffffffffu, sA, off);
            qA += __shfl_xor_sync(0xffffffffu, qA, off);
            sB += __shfl_xor_sync(0xffffffffu, sB, off);
            qB += __shfl_xor_sync(0xffffffffu, qB, off);
            #pragma unroll
            for (int gh = 0; gh < 2; gh++) {
                mxA[gh] = fmaxf(mxA[gh], __shfl_xor_sync(0xffffffffu, mxA[gh], off));
                mxB[gh] = fmaxf(mxB[gh], __shfl_xor_sync(0xffffffffu, mxB[gh], off));
            }
        }
        if (q == 0) {
            int lmA = m0w + im*16 + r4, lmB = lmA + 8;
            if (!WRITE_G) {
                size_t g0 = (size_t)ntile*4 + (n0w >> 5);
                Fmax[g0*COUT + mbase + lmA]     = mxA[0];
                Fmax[(g0+1)*COUT + mbase + lmA] = mxA[1];
                Fmax[g0*COUT + mbase + lmB]     = mxB[0];
                Fmax[(g0+1)*COUT + mbase + lmB] = mxB[1];
            }
            atomicAdd(&sred[lmA], sA); atomicAdd(&qred[lmA], qA);
            atomicAdd(&sred[lmB], sB); atomicAdd(&qred[lmB], qB);
        }
    }
    __syncthreads();
    if (t < 128) {
        int slot = (ntile + mtile) & (NSLOT-1);
        atomicAdd(&psum[slot*CMAX + mbase + t], (double)sred[t]);
        atomicAdd(&psq [slot*CMAX + mbase + t], (double)qred[t]);
    }
    __threadfence();
    __syncthreads();
    if (t == 0) lastf = (atomicAdd(ctr, 1) == nctas - 1) ? 1 : 0;
    __syncthreads();
    if (lastf && t < COUT) bn_finalize(psum, psq, osc, obi, t, invM);
}

// ---------------- final output f2 ----------------
__global__ void k_out_f2(const float* __restrict__ Fmax, const float* __restrict__ sc,
                         const float* __restrict__ bi, float* __restrict__ out)
{
    size_t i = (size_t)blockIdx.x*256 + threadIdx.x;
    int s = (int)(i & 255);
    size_t r = i >> 8;
    int c = (int)(r & 255);
    int b = (int)(r >> 8);
    float v = Fmax[((size_t)(b*256 + s))*256 + c]*sc[c] + bi[c];
    out[24576 + i] = fmaxf(v, 0.f);
}

// ---------------- launch ----------------
extern "C" void kernel_launch(void* const* d_in, const int* in_sizes, int n_in,
                              void* d_out, int out_size)
{
    const float* x  = (const float*)d_in[0];
    const float* w1 = (const float*)d_in[1];
    const float* w2 = (const float*)d_in[2];
    const float* wa = (const float*)d_in[3];
    const float* wb = (const float*)d_in[4];
    const float* wc = (const float*)d_in[5];
    const float* wd = (const float*)d_in[6];

    void *pF0, *pF1t, *pnx1, *pfps1, *pgi1, *pF1max, *pnx2, *pfps2, *pgi2, *pF2max;
    void *pAh, *pAl, *pG, *pWh, *pWl, *ppsum, *ppsq, *pscale, *pbias, *pctr;
    cudaGetSymbolAddress(&pF0, g_F0);       cudaGetSymbolAddress(&pF1t, g_F1t);
    cudaGetSymbolAddress(&pnx1, g_nx1);     cudaGetSymbolAddress(&pfps1, g_fps1);
    cudaGetSymbolAddress(&pgi1, g_gi1);     cudaGetSymbolAddress(&pF1max, g_F1max);
    cudaGetSymbolAddress(&pnx2, g_nx2);     cudaGetSymbolAddress(&pfps2, g_fps2);
    cudaGetSymbolAddress(&pgi2, g_gi2);     cudaGetSymbolAddress(&pF2max, g_F2max);
    cudaGetSymbolAddress(&pAh, g_Ah);       cudaGetSymbolAddress(&pAl, g_Al);
    cudaGetSymbolAddress(&pG, g_G);
    cudaGetSymbolAddress(&pWh, g_Wh);       cudaGetSymbolAddress(&pWl, g_Wl);
    cudaGetSymbolAddress(&ppsum, g_psum);   cudaGetSymbolAddress(&ppsq, g_psq);
    cudaGetSymbolAddress(&pscale, g_scale); cudaGetSymbolAddress(&pbias, g_bias);
    cudaGetSymbolAddress(&pctr, g_ctr);

    double* psum = (double*)ppsum;
    double* psq  = (double*)ppsq;
    float* scl = (float*)pscale;
    float* bia = (float*)pbias;
    __nv_bfloat16* Ah = (__nv_bfloat16*)pAh;
    __nv_bfloat16* Al = (__nv_bfloat16*)pAl;
    float* G = (float*)pG;
    __nv_bfloat16* Wh = (__nv_bfloat16*)pWh;
    __nv_bfloat16* Wl = (__nv_bfloat16*)pWl;
    int* ctr = (int*)pctr;
    float* nx1 = (float*)pnx1;
    float* nx2 = (float*)pnx2;

    const int FPS1SM = 2*3*N1*4 + 2*3*8;   // 49200 bytes
    cudaFuncSetAttribute(k_conv1fps, cudaFuncAttributeMaxDynamicSharedMemorySize, FPS1SM);

    cudaMemsetAsync(psum, 0, 6*NSLOT*CMAX*sizeof(double), 0);
    cudaMemsetAsync(psq,  0, 6*NSLOT*CMAX*sizeof(double), 0);
    cudaMemsetAsync(ctr,  0, 8*sizeof(int), 0);

    k_wsplit<<<640,256>>>(wa, wb, wc, wd, Wh, Wl);

    // conv1 + fps1 (16 dual-fps blocks first)
    k_conv1fps<<<16 + 2048, 256, FPS1SM>>>(x, w1, (float*)pF0, psum, psq, ctr + 0, scl, bia,
                                           (int*)pfps1, nx1);
    // conv2 + ball1 (ball blocks first)
    k_conv2ball<<<2048 + 1024, 256>>>((const float*)pF0, w2, scl, bia,
                                      (float*)pF1t, psum + NSLOT*CMAX, psq + NSLOT*CMAX,
                                      ctr + 1, scl + CMAX, bia + CMAX,
                                      x, nx1, (int*)pgi1);
    // gather1 + fps2 (16 dual-fps blocks first)
    k_gather1fps2<<<16 + BB*S1, 256>>>((const float*)pF1t, scl + CMAX, bia + CMAX,
                                       (const int*)pgi1, (const int*)pfps1, Ah, Al,
                                       nx1, (int*)pfps2, nx2);
    // ball2
    k_ball2<<<BB*S2/8, 256>>>(nx1, nx2, (int*)pgi2);

    // sg1 GEMMs
    k_mma<128,128,true,false,true><<<dim3(NT1/128,1), 256>>>(Wh + 0, Wl + 0,
        nullptr, Ah, Al, nullptr, nullptr,
        G, nullptr, psum + 2*NSLOT*CMAX, psq + 2*NSLOT*CMAX,
        ctr + 2, NT1/128, 1.0/((double)NT1), scl + 2*CMAX, bia + 2*CMAX);
    k_mma<128,128,false,true,false><<<dim3(NT1/128,1), 256>>>(Wh + 16384, Wl + 16384,
        G, nullptr, nullptr, scl + 2*CMAX, bia + 2*CMAX,
        nullptr, (float*)pF1max, psum + 3*NSLOT*CMAX, psq + 3*NSLOT*CMAX,
        ctr + 3, NT1/128, 1.0/((double)NT1), scl + 3*CMAX, bia + 3*CMAX);

    // gather2
    k_gather2<<<BB*S2, 256>>>((const float*)pF1max, scl + 3*CMAX, bia + 3*CMAX,
                              (const int*)pgi2, (const int*)pfps2, Ah, Al);

    // sg2 GEMMs
    k_mma<256,256,true,false,true><<<dim3(NT2/128,2), 256>>>(Wh + 32768, Wl + 32768,
        nullptr, Ah, Al, nullptr, nullptr,
        G, nullptr, psum + 4*NSLOT*CMAX, psq + 4*NSLOT*CMAX,
        ctr + 4, (NT2/128)*2, 1.0/((double)NT2), scl + 4*CMAX, bia + 4*CMAX);
    k_mma<256,256,false,true,false><<<dim3(NT2/128,2), 256>>>(Wh + 98304, Wl + 98304,
        G, nullptr, nullptr, scl + 4*CMAX, bia + 4*CMAX,
        nullptr, (float*)pF2max, psum + 5*NSLOT*CMAX, psq + 5*NSLOT*CMAX,
        ctr + 5, (NT2/128)*2, 1.0/((double)NT2), scl + 5*CMAX, bia + 5*CMAX);

    // outputs
    cudaMemcpyAsync(d_out, pnx2, (size_t)BB*S2*3*sizeof(float), cudaMemcpyDeviceToDevice, 0);
    k_out_f2<<<(BB*256*256)/256, 256>>>((const float*)pF2max, scl + 5*CMAX, bia + 5*CMAX, (float*)d_out);
}

// round 17
// speedup vs baseline: 1.0786x; 1.0786x over previous
#include <cuda_runtime.h>
#include <cuda_bf16.h>
#include <cstdint>
#include <cstddef>

#define BB 32
#define N1 2048
#define S1 512
#define S2 256
#define NS 32
#define R2C 0.25f
#define NSLOT 32
#define CMAX 256
#define NT1 (BB*S1*NS)
#define NT2 (BB*S2*NS)
#define POOLE 67108864ull

// ---------------- static device buffers ----------------
__device__ float g_F0[(size_t)BB*64*N1];
__device__ float g_F1t[(size_t)BB*N1*64];
__device__ float g_nx1[(size_t)BB*S1*3];
__device__ int   g_fps1[BB*S1];
__device__ int   g_gi1[(size_t)BB*S1*NS];
__device__ float g_F1max[(size_t)BB*S1*128];
__device__ float g_nx2[(size_t)BB*S2*3];
__device__ int   g_fps2[BB*S2];
__device__ int   g_gi2[(size_t)BB*S2*NS];
__device__ float g_F2max[(size_t)BB*S2*256];

__device__ __nv_bfloat16 g_Ah[POOLE];
__device__ __nv_bfloat16 g_Al[POOLE];
__device__ float g_G[POOLE];
__device__ __nv_bfloat16 g_Wh[163840];
__device__ __nv_bfloat16 g_Wl[163840];

__device__ double g_psum[6*NSLOT*CMAX];
__device__ double g_psq [6*NSLOT*CMAX];
__device__ float  g_scale[6*CMAX];
__device__ float  g_bias [6*CMAX];
__device__ int    g_ctr[8];

// ---------------- helpers ----------------
__device__ __forceinline__ void mma16816(float* c, const uint32_t* a, uint32_t b0, uint32_t b1) {
    asm volatile("mma.sync.aligned.m16n8k16.row.col.f32.bf16.bf16.f32 "
        "{%0,%1,%2,%3}, {%4,%5,%6,%7}, {%8,%9}, {%0,%1,%2,%3};"
        : "+f"(c[0]), "+f"(c[1]), "+f"(c[2]), "+f"(c[3])
        : "r"(a[0]), "r"(a[1]), "r"(a[2]), "r"(a[3]), "r"(b0), "r"(b1));
}

#define LDSMX4(r, addr) \
    asm volatile("ldmatrix.sync.aligned.m8n8.x4.shared.b16 {%0,%1,%2,%3}, [%4];" \
        : "=r"((r)[0]), "=r"((r)[1]), "=r"((r)[2]), "=r"((r)[3]) : "r"(addr))

__device__ __forceinline__ void split2(float a, float b, uint32_t& hi, uint32_t& lo)
{
    __nv_bfloat162 h = __floats2bfloat162_rn(a, b);
    float2 f = __bfloat1622float2(h);
    __nv_bfloat162 l = __floats2bfloat162_rn(a - f.x, b - f.y);
    hi = *reinterpret_cast<uint32_t*>(&h);
    lo = *reinterpret_cast<uint32_t*>(&l);
}
__device__ __forceinline__ void split4(float v0, float v1, float v2, float v3,
                                       uint2& hi, uint2& lo)
{
    split2(v0, v1, hi.x, lo.x);
    split2(v2, v3, hi.y, lo.y);
}

__device__ __forceinline__ void bn_finalize(const double* psum, const double* psq,
                                            float* sc, float* bi, int t, double invM)
{
    double s = 0.0, q = 0.0;
    for (int k = 0; k < NSLOT; k++) {
        s += __ldcg(&psum[k*CMAX + t]);
        q += __ldcg(&psq [k*CMAX + t]);
    }
    double mean = s * invM;
    double var  = q * invM - mean * mean;
    if (var < 0.0) var = 0.0;
    double sv = 1.0 / sqrt(var + 1e-5);
    sc[t] = (float)sv;
    bi[t] = (float)(-mean * sv);
}

// ---------------- FPS body (exact fp arithmetic vs reference; R14 form) ----------------
template<int N, int S>
__device__ __forceinline__ void fps_body(
    const float* __restrict__ Pb, int pstride, int cstride,
    int* __restrict__ outIdx, float* __restrict__ outXYZ, int b,
    float* xs, float* ys, float* zs, float (*wv)[8], int (*wi)[8])
{
    constexpr int PPT = N/256;
    int t = threadIdx.x, wid = t >> 5, lane = t & 31;
    for (int j = t; j < N; j += 256) {
        xs[j] = Pb[(size_t)j*pstride];
        ys[j] = Pb[(size_t)j*pstride + cstride];
        zs[j] = Pb[(size_t)j*pstride + 2*cstride];
    }
    float dist[PPT];
    #pragma unroll
    for (int i = 0; i < PPT; i++) dist[i] = 1e10f;
    __syncthreads();
    int far = 0;
    for (int s = 0; s < S; s++) {
        float fx = xs[far], fy = ys[far], fz = zs[far];
        if (t == 0) {
            outIdx[(size_t)b*S + s] = far;
            float* o = &outXYZ[((size_t)b*S + s)*3];
            o[0] = fx; o[1] = fy; o[2] = fz;
        }
        float bv = -1.f; int bi = 0x7fffffff;
        #pragma unroll
        for (int i = 0; i < PPT; i++) {
            int j = i*256 + t;
            float dx = __fsub_rn(xs[j], fx);
            float dy = __fsub_rn(ys[j], fy);
            float dz = __fsub_rn(zs[j], fz);
            float d = __fadd_rn(__fadd_rn(__fmul_rn(dx,dx), __fmul_rn(dy,dy)), __fmul_rn(dz,dz));
            float nd = fminf(dist[i], d);
            dist[i] = nd;
            if (nd > bv) { bv = nd; bi = j; }
        }
        #pragma unroll
        for (int off = 16; off; off >>= 1) {
            float ov = __shfl_down_sync(0xffffffffu, bv, off);
            int   oi = __shfl_down_sync(0xffffffffu, bi, off);
            if (ov > bv || (ov == bv && oi < bi)) { bv = ov; bi = oi; }
        }
        int p = s & 1;
        if (lane == 0) { wv[p][wid] = bv; wi[p][wid] = bi; }
        __syncthreads();
        float best = wv[p][0]; int besti = wi[p][0];
        #pragma unroll
        for (int k = 1; k < 8; k++) {
            float v2 = wv[p][k]; int i2 = wi[p][k];
            if (v2 > best || (v2 == best && i2 < besti)) { best = v2; besti = i2; }
        }
        far = besti;
    }
}

// ---------------- ball body (one warp per group) ----------------
__device__ __forceinline__ void ball_body(
    const float* __restrict__ Cb, int pstride, int cstride, int N,
    float qx, float qy, float qz, int* buf, int lane, int* __restrict__ giout)
{
    int cnt = 0;
    for (int base = 0; base < N && cnt < NS; base += 32) {
        int j = base + lane;
        float dx = __fsub_rn(Cb[(size_t)j*pstride], qx);
        float dy = __fsub_rn(Cb[(size_t)j*pstride + cstride], qy);
        float dz = __fsub_rn(Cb[(size_t)j*pstride + 2*cstride], qz);
        float d = __fadd_rn(__fadd_rn(__fmul_rn(dx,dx), __fmul_rn(dy,dy)), __fmul_rn(dz,dz));
        bool ok = !(d > R2C);
        unsigned m = __ballot_sync(0xffffffffu, ok);
        int pos = cnt + __popc(m & ((1u << lane) - 1u));
        if (ok && pos < NS) buf[pos] = j;
        cnt += __popc(m);
    }
    __syncwarp();
    int first = buf[0];
    int mm = cnt < NS ? cnt : NS;
    int v = (lane < mm) ? buf[lane] : first;
    giout[lane] = v;
}

// ---------------- gather body: bf16 hi/lo A, [col][CIN] K-major ----------------
template<int CH>
__device__ __forceinline__ void gather_body(
    const float* __restrict__ src, int NP,
    const float* __restrict__ sc, const float* __restrict__ bi,
    const int* __restrict__ gi, const int* __restrict__ fpsidx, int S,
    __nv_bfloat16* __restrict__ Ah, __nv_bfloat16* __restrict__ Al, int g,
    float* fc, uint32_t* fch, uint32_t* fcl, int* gix)
{
    constexpr int CIN = 2*CH;
    int t = threadIdx.x, wid = t >> 5, lane = t & 31;
    int b = g / S, s = g % S;
    if (t < 32) gix[t] = gi[(size_t)g*NS + t];
    if (t < CH) {
        int ci = fpsidx[(size_t)b*S + s];
        float v = src[((size_t)b*NP + ci)*CH + t]*sc[t] + bi[t];
        fc[t] = fmaxf(v, 0.f);
    }
    __syncthreads();
    if (t < CH/2) split2(fc[2*t], fc[2*t+1], fch[t], fcl[t]);
    __syncthreads();
    for (int k = wid; k < NS; k += 8) {
        size_t row = (size_t)b*NP + gix[k];
        size_t ob = ((size_t)g*NS + k)*CIN;
        for (int cp = lane; cp < CH/2; cp += 32) {
            int c = 2*cp;
            float2 sv = *(const float2*)&src[row*CH + c];
            float v0 = fmaxf(sv.x*sc[c]   + bi[c],   0.f);
            float v1 = fmaxf(sv.y*sc[c+1] + bi[c+1], 0.f);
            uint32_t h, l;
            split2(v0 - fc[c], v1 - fc[c+1], h, l);
            *(uint32_t*)&Ah[ob + c] = h;
            *(uint32_t*)&Al[ob + c] = l;
            *(uint32_t*)&Ah[ob + CH + c] = fch[cp];
            *(uint32_t*)&Al[ob + CH + c] = fcl[cp];
        }
    }
}

// ---------------- fused weight split fp32 -> bf16 hi/lo ----------------
__global__ void k_wsplit(const float* __restrict__ wa, const float* __restrict__ wb,
                         const float* __restrict__ wc, const float* __restrict__ wd,
                         __nv_bfloat16* __restrict__ Wh, __nv_bfloat16* __restrict__ Wl)
{
    int i = blockIdx.x*256 + threadIdx.x;
    if (i >= 163840) return;
    float v;
    if (i < 16384)      v = wa[i];
    else if (i < 32768) v = wb[i - 16384];
    else if (i < 98304) v = wc[i - 32768];
    else                v = wd[i - 98304];
    __nv_bfloat16 h = __float2bfloat16(v);
    Wh[i] = h;
    Wl[i] = __float2bfloat16(v - __bfloat162float(h));
}

// ---------------- conv1 + fps1 fused (fps blocks FIRST; R14 form) ----------------
__global__ void __launch_bounds__(256) k_conv1fps(
    const float* __restrict__ x, const float* __restrict__ W,
    float* __restrict__ F0, double* __restrict__ psum, double* __restrict__ psq,
    int* __restrict__ ctr, float* __restrict__ osc, float* __restrict__ obi,
    int* __restrict__ fps1, float* __restrict__ nx1)
{
    __shared__ float xs[N1], ys[N1], zs[N1];
    __shared__ float wvs[2][8]; __shared__ int wis[2][8];
    __shared__ float ws_[8], wq_[8];
    __shared__ int lastf;
    int bid = blockIdx.x, t = threadIdx.x;
    if (bid < 32) {
        fps_body<N1,S1>(x + (size_t)bid*3*N1, 1, N1, fps1, nx1, bid, xs, ys, zs, wvs, wis);
        return;
    }
    int cb = bid - 32;
    int c = cb & 63, b = cb >> 6;
    float w0 = W[c*3], w1 = W[c*3+1], w2 = W[c*3+2];
    const float* xb = x + (size_t)b*3*N1;
    float* o = F0 + ((size_t)b*64 + c)*N1;
    float ls = 0.f, lq = 0.f;
    for (int n = t; n < N1; n += 256) {
        float v = w0*xb[n] + w1*xb[N1+n] + w2*xb[2*N1+n];
        o[n] = v; ls += v; lq += v*v;
    }
    for (int off = 16; off; off >>= 1) {
        ls += __shfl_down_sync(0xffffffffu, ls, off);
        lq += __shfl_down_sync(0xffffffffu, lq, off);
    }
    if ((t & 31) == 0) { ws_[t >> 5] = ls; wq_[t >> 5] = lq; }
    __syncthreads();
    if (t == 0) {
        float S = 0.f, Q = 0.f;
        for (int i = 0; i < 8; i++) { S += ws_[i]; Q += wq_[i]; }
        atomicAdd(&psum[(b & (NSLOT-1))*CMAX + c], (double)S);
        atomicAdd(&psq [(b & (NSLOT-1))*CMAX + c], (double)Q);
        __threadfence();
        lastf = (atomicAdd(ctr, 1) == 2048 - 1) ? 1 : 0;
    }
    __syncthreads();
    if (lastf && t < 64) bn_finalize(psum, psq, osc, obi, t, 1.0/((double)BB*N1));
}

// ---------------- conv2 + ball1 + fps2 fused (fps2 FIRST, then ball, then conv) ----------------
__global__ void __launch_bounds__(256) k_conv2ball(
    const float* __restrict__ F0, const float* __restrict__ W,
    const float* __restrict__ sc0, const float* __restrict__ bi0,
    float* __restrict__ F1t, double* __restrict__ psum, double* __restrict__ psq,
    int* __restrict__ ctr, float* __restrict__ osc, float* __restrict__ obi,
    const float* __restrict__ x, const float* __restrict__ nx1, int* __restrict__ gi1,
    int* __restrict__ fps2, float* __restrict__ nx2)
{
    __shared__ float in_t[64*64];
    __shared__ float ws[64*65];
    __shared__ float pspart[4*64], pqpart[4*64];
    __shared__ int lastf;
    __shared__ int bbuf[8][NS];
    __shared__ float fpsm[3*S1];
    __shared__ float wvs[2][8]; __shared__ int wis[2][8];
    int bid = blockIdx.x, t = threadIdx.x;
    if (bid < 32) {
        fps_body<S1,S2>(nx1 + (size_t)bid*S1*3, 3, 1, fps2, nx2, bid,
                        fpsm, fpsm + S1, fpsm + 2*S1, wvs, wis);
        return;
    }
    if (bid < 32 + 2048) {
        int wid = t >> 5, lane = t & 31;
        int g = (bid - 32)*8 + wid;
        int b = g / S1;
        const float* q = nx1 + (size_t)g*3;
        ball_body(x + (size_t)b*3*N1, 1, N1, N1, q[0], q[1], q[2],
                  bbuf[wid], lane, gi1 + (size_t)g*NS);
        return;
    }
    int cb = bid - 32 - 2048;
    int tile = cb & 31, b = cb >> 5;
    for (int i = t; i < 4096; i += 256) { int c = i >> 6, k = i & 63; ws[c*65 + k] = W[i]; }
    const float* F0b = F0 + (size_t)b*64*N1 + tile*64;
    for (int i = t; i < 4096; i += 256) {
        int k = i >> 6, nn = i & 63;
        float v = F0b[(size_t)k*N1 + nn]*sc0[k] + bi0[k];
        in_t[k*64 + nn] = fmaxf(v, 0.f);
    }
    __syncthreads();
    int c = t & 63, nq = t >> 6;
    float acc[16];
    #pragma unroll
    for (int j = 0; j < 16; j++) acc[j] = 0.f;
    for (int k = 0; k < 64; k++) {
        float wv = ws[c*65 + k];
        const float* ar = &in_t[k*64 + nq*16];
        #pragma unroll
        for (int jq = 0; jq < 4; jq++) {
            float4 a = *(const float4*)(ar + 4*jq);
            acc[4*jq+0] += wv*a.x; acc[4*jq+1] += wv*a.y;
            acc[4*jq+2] += wv*a.z; acc[4*jq+3] += wv*a.w;
        }
    }
    float lsum = 0.f, lsq = 0.f;
    #pragma unroll
    for (int j = 0; j < 16; j++) { float v = acc[j]; lsum += v; lsq += v*v; }
    pspart[nq*64 + c] = lsum; pqpart[nq*64 + c] = lsq;
    __syncthreads();
    #pragma unroll
    for (int j = 0; j < 16; j++) ws[(nq*16 + j)*65 + c] = acc[j];
    if (t < 64) {
        float s = pspart[t] + pspart[64+t] + pspart[128+t] + pspart[192+t];
        float q = pqpart[t] + pqpart[64+t] + pqpart[128+t] + pqpart[192+t];
        int slot = cb & (NSLOT-1);
        atomicAdd(&psum[slot*CMAX + t], (double)s);
        atomicAdd(&psq [slot*CMAX + t], (double)q);
    }
    __syncthreads();
    size_t nbase = (size_t)b*N1 + tile*64;
    for (int i = t; i < 4096; i += 256) {
        int n = i >> 6, cc = i & 63;
        F1t[(nbase + n)*64 + cc] = ws[n*65 + cc];
    }
    if (t == 0) {
        __threadfence();
        lastf = (atomicAdd(ctr, 1) == 1024 - 1) ? 1 : 0;
    }
    __syncthreads();
    if (lastf && t < 64) bn_finalize(psum, psq, osc, obi, t, 1.0/((double)BB*N1));
}

// ---------------- gather1 standalone ----------------
__global__ void __launch_bounds__(256) k_gather1(
    const float* __restrict__ F1t, const float* __restrict__ sc, const float* __restrict__ bi,
    const int* __restrict__ gi1, const int* __restrict__ fps1,
    __nv_bfloat16* __restrict__ Ah, __nv_bfloat16* __restrict__ Al)
{
    __shared__ float fc[64]; __shared__ uint32_t fch[32], fcl[32]; __shared__ int gix[32];
    gather_body<64>(F1t, N1, sc, bi, gi1, fps1, S1, Ah, Al, blockIdx.x, fc, fch, fcl, gix);
}

// ---------------- ball2 (8 warps/block) ----------------
__global__ void __launch_bounds__(256) k_ball2(
    const float* __restrict__ nx1, const float* __restrict__ nx2, int* __restrict__ gi2)
{
    __shared__ int bbuf[8][NS];
    int wid = threadIdx.x >> 5, lane = threadIdx.x & 31;
    int g = blockIdx.x*8 + wid;
    int b = g / S2;
    const float* q = nx2 + (size_t)g*3;
    ball_body(nx1 + (size_t)b*S1*3, 3, 1, S1, q[0], q[1], q[2],
              bbuf[wid], lane, gi2 + (size_t)g*NS);
}

// ---------------- gather2 standalone ----------------
__global__ void __launch_bounds__(256) k_gather2(
    const float* __restrict__ F1max, const float* __restrict__ sc, const float* __restrict__ bi,
    const int* __restrict__ gi2, const int* __restrict__ fps2,
    __nv_bfloat16* __restrict__ Ah, __nv_bfloat16* __restrict__ Al)
{
    __shared__ float fc[128]; __shared__ uint32_t fch[64], fcl[64]; __shared__ int gix[32];
    gather_body<128>(F1max, S1, sc, bi, gi2, fps2, S2, Ah, Al, blockIdx.x, fc, fch, fcl, gix);
}

// ---------------- bf16 3-pass mma.sync GEMM (unchanged from measured-1646) ----------------
template<int K, int COUT, bool WRITE_G, bool BN, bool PRESPLIT>
__global__ void __launch_bounds__(256, 2) k_mma(
    const __nv_bfloat16* __restrict__ Wh, const __nv_bfloat16* __restrict__ Wl,
    const float* __restrict__ A32,
    const __nv_bfloat16* __restrict__ Ah, const __nv_bfloat16* __restrict__ Al,
    const float* __restrict__ bnsc, const float* __restrict__ bnbi,
    float* __restrict__ G, float* __restrict__ Fmax,
    double* __restrict__ psum, double* __restrict__ psq,
    int* __restrict__ ctr, int nctas, double invM,
    float* __restrict__ osc, float* __restrict__ obi)
{
    __shared__ __align__(16) __nv_bfloat16 Wht[128*40];
    __shared__ __align__(16) __nv_bfloat16 Wlt[128*40];
    __shared__ __align__(16) __nv_bfloat16 Aht[128*40];
    __shared__ __align__(16) __nv_bfloat16 Alt[128*40];
    __shared__ float sred[128], qred[128];
    __shared__ float scs[256], bis[256];
    __shared__ int lastf;

    int t = threadIdx.x, wid = t >> 5, lane = t & 31;
    int r4 = lane >> 2, q = lane & 3;
    int ntile = blockIdx.x, mtile = blockIdx.y;
    size_t colbase = (size_t)ntile*128;
    int mbase = mtile*128;
    int m0w = (wid & 3)*32, n0w = (wid >> 2)*64;

    for (int i = t; i < 128; i += 256) { sred[i] = 0.f; qred[i] = 0.f; }
    if (BN) for (int i = t; i < K; i += 256) { scs[i] = bnsc[i]; bis[i] = bnbi[i]; }

    float acc[2][8][4];
    #pragma unroll
    for (int im = 0; im < 2; im++)
        #pragma unroll
        for (int in_ = 0; in_ < 8; in_++)
            #pragma unroll
            for (int c = 0; c < 4; c++) acc[im][in_][c] = 0.f;

    constexpr int NCH = K/32;

    uint32_t whB = (uint32_t)__cvta_generic_to_shared(Wht);
    uint32_t wlB = (uint32_t)__cvta_generic_to_shared(Wlt);
    uint32_t ahB = (uint32_t)__cvta_generic_to_shared(Aht);
    uint32_t alB = (uint32_t)__cvta_generic_to_shared(Alt);
    uint32_t aOff = (uint32_t)(((m0w + (lane & 15))*40 + (lane >> 4)*8)*2);
    uint32_t bOff = (uint32_t)(((((lane & 7) + ((lane >> 4) << 3)) + n0w)*40 + ((lane >> 3) & 1)*8)*2);

    uint4 pa[4];
    uint4 pah[2], pal[2];
    if (PRESPLIT) {
        #pragma unroll
        for (int i = 0; i < 2; i++) {
            int idx = t + 256*i, row = idx >> 2, seg = idx & 3;
            pah[i] = *(const uint4*)(Ah + (colbase + row)*(size_t)K + seg*8);
            pal[i] = *(const uint4*)(Al + (colbase + row)*(size_t)K + seg*8);
        }
    } else {
        #pragma unroll
        for (int i = 0; i < 4; i++) {
            int idx = t + 256*i, row = idx >> 3, seg = idx & 7;
            pa[i] = *(const uint4*)(A32 + (colbase + row)*(size_t)K + seg*4);
        }
    }

    #pragma unroll 1
    for (int kc = 0; kc < NCH; kc++) {
        __syncthreads();
        if (PRESPLIT) {
            #pragma unroll
            for (int i = 0; i < 2; i++) {
                int idx = t + 256*i, row = idx >> 2, seg = idx & 3;
                *(uint4*)&Aht[row*40 + seg*8] = pah[i];
                *(uint4*)&Alt[row*40 + seg*8] = pal[i];
            }
        } else {
            #pragma unroll
            for (int i = 0; i < 4; i++) {
                int idx = t + 256*i, row = idx >> 3, seg = idx & 7;
                float4 f = *(float4*)&pa[i];
                if (BN) {
                    int kb = kc*32 + seg*4;
                    f.x = fmaxf(f.x*scs[kb]   + bis[kb],   0.f);
                    f.y = fmaxf(f.y*scs[kb+1] + bis[kb+1], 0.f);
                    f.z = fmaxf(f.z*scs[kb+2] + bis[kb+2], 0.f);
                    f.w = fmaxf(f.w*scs[kb+3] + bis[kb+3], 0.f);
                }
                uint2 hi, lo;
                split4(f.x, f.y, f.z, f.w, hi, lo);
                *(uint2*)&Aht[row*40 + seg*4] = hi;
                *(uint2*)&Alt[row*40 + seg*4] = lo;
            }
        }
        #pragma unroll
        for (int i = 0; i < 2; i++) {
            int idx = t + 256*i, row = idx >> 2, seg = idx & 3;
            *(uint4*)&Wht[row*40 + seg*8] =
                *(const uint4*)(Wh + (size_t)(mbase + row)*K + kc*32 + seg*8);
            *(uint4*)&Wlt[row*40 + seg*8] =
                *(const uint4*)(Wl + (size_t)(mbase + row)*K + kc*32 + seg*8);
        }
        __syncthreads();
        if (kc + 1 < NCH) {
            if (PRESPLIT) {
                #pragma unroll
                for (int i = 0; i < 2; i++) {
                    int idx = t + 256*i, row = idx >> 2, seg = idx & 3;
                    pah[i] = *(const uint4*)(Ah + (colbase + row)*(size_t)K + (kc+1)*32 + seg*8);
                    pal[i] = *(const uint4*)(Al + (colbase + row)*(size_t)K + (kc+1)*32 + seg*8);
                }
            } else {
                #pragma unroll
                for (int i = 0; i < 4; i++) {
                    int idx = t + 256*i, row = idx >> 3, seg = idx & 7;
                    pa[i] = *(const uint4*)(A32 + (colbase + row)*(size_t)K + (kc+1)*32 + seg*4);
                }
            }
        }
        #pragma unroll
        for (int kk = 0; kk < 2; kk++) {
            uint32_t akk = aOff + kk*32;
            uint32_t ah0[4], ah1[4], al0[4], al1[4];
            LDSMX4(ah0, whB + akk);
            LDSMX4(ah1, whB + akk + 1280);
            LDSMX4(al0, wlB + akk);
            LDSMX4(al1, wlB + akk + 1280);
            #pragma unroll
            for (int inp = 0; inp < 4; inp++) {
                uint32_t bkk = bOff + (uint32_t)((inp*16*40 + kk*16)*2);
                uint32_t bh[4], bl[4];
                LDSMX4(bh, ahB + bkk);
                LDSMX4(bl, alB + bkk);
                mma16816(acc[0][2*inp],   ah0, bh[0], bh[1]);
                mma16816(acc[1][2*inp],   ah1, bh[0], bh[1]);
                mma16816(acc[0][2*inp],   ah0, bl[0], bl[1]);
                mma16816(acc[1][2*inp],   ah1, bl[0], bl[1]);
                mma16816(acc[0][2*inp],   al0, bh[0], bh[1]);
                mma16816(acc[1][2*inp],   al1, bh[0], bh[1]);
                mma16816(acc[0][2*inp+1], ah0, bh[2], bh[3]);
                mma16816(acc[1][2*inp+1], ah1, bh[2], bh[3]);
                mma16816(acc[0][2*inp+1], ah0, bl[2], bl[3]);
                mma16816(acc[1][2*inp+1], ah1, bl[2], bl[3]);
                mma16816(acc[0][2*inp+1], al0, bh[2], bh[3]);
                mma16816(acc[1][2*inp+1], al1, bh[2], bh[3]);
            }
        }
    }

    // ---------------- epilogue ----------------
    if (WRITE_G) {
        #pragma unroll
        for (int im = 0; im < 2; im++)
            #pragma unroll
            for (int in_ = 0; in_ < 8; in_++) {
                size_t col = colbase + n0w + in_*8 + q*2;
                int mA = mbase + m0w + im*16 + r4;
                G[col*COUT + mA]       = acc[im][in_][0];
                G[(col+1)*COUT + mA]   = acc[im][in_][1];
                G[col*COUT + mA + 8]   = acc[im][in_][2];
                G[(col+1)*COUT + mA+8] = acc[im][in_][3];
            }
    }
    #pragma unroll
    for (int im = 0; im < 2; im++) {
        float sA = 0.f, sB = 0.f, qA = 0.f, qB = 0.f;
        float mxA[2] = {-3.4e38f, -3.4e38f}, mxB[2] = {-3.4e38f, -3.4e38f};
        #pragma unroll
        for (int in_ = 0; in_ < 8; in_++) {
            int gh = in_ >> 2;
            float v0 = acc[im][in_][0], v1 = acc[im][in_][1];
            float v2 = acc[im][in_][2], v3 = acc[im][in_][3];
            sA += v0 + v1; qA += v0*v0 + v1*v1;
            sB += v2 + v3; qB += v2*v2 + v3*v3;
            mxA[gh] = fmaxf(mxA[gh], fmaxf(v0, v1));
            mxB[gh] = fmaxf(mxB[gh], fmaxf(v2, v3));
        }
        #pragma unroll
        for (int off = 1; off <= 2; off <<= 1) {
            sA += __shfl_xor_sync(0xffffffffu, sA, off);
            qA += __shfl_xor_sync(0xffffffffu, qA, off);
            sB += __shfl_xor_sync(0xffffffffu, sB, off);
            qB += __shfl_xor_sync(0xffffffffu, qB, off);
            #pragma unroll
            for (int gh = 0; gh < 2; gh++) {
                mxA[gh] = fmaxf(mxA[gh], __shfl_xor_sync(0xffffffffu, mxA[gh], off));
                mxB[gh] = fmaxf(mxB[gh], __shfl_xor_sync(0xffffffffu, mxB[gh], off));
            }
        }
        if (q == 0) {
            int lmA = m0w + im*16 + r4, lmB = lmA + 8;
            if (!WRITE_G) {
                size_t g0 = (size_t)ntile*4 + (n0w >> 5);
                Fmax[g0*COUT + mbase + lmA]     = mxA[0];
                Fmax[(g0+1)*COUT + mbase + lmA] = mxA[1];
                Fmax[g0*COUT + mbase + lmB]     = mxB[0];
                Fmax[(g0+1)*COUT + mbase + lmB] = mxB[1];
            }
            atomicAdd(&sred[lmA], sA); atomicAdd(&qred[lmA], qA);
            atomicAdd(&sred[lmB], sB); atomicAdd(&qred[lmB], qB);
        }
    }
    __syncthreads();
    if (t < 128) {
        int slot = (ntile + mtile) & (NSLOT-1);
        atomicAdd(&psum[slot*CMAX + mbase + t], (double)sred[t]);
        atomicAdd(&psq [slot*CMAX + mbase + t], (double)qred[t]);
    }
    __threadfence();
    __syncthreads();
    if (t == 0) lastf = (atomicAdd(ctr, 1) == nctas - 1) ? 1 : 0;
    __syncthreads();
    if (lastf && t < COUT) bn_finalize(psum, psq, osc, obi, t, invM);
}

// ---------------- final output f2 ----------------
__global__ void k_out_f2(const float* __restrict__ Fmax, const float* __restrict__ sc,
                         const float* __restrict__ bi, float* __restrict__ out)
{
    size_t i = (size_t)blockIdx.x*256 + threadIdx.x;
    int s = (int)(i & 255);
    size_t r = i >> 8;
    int c = (int)(r & 255);
    int b = (int)(r >> 8);
    float v = Fmax[((size_t)(b*256 + s))*256 + c]*sc[c] + bi[c];
    out[24576 + i] = fmaxf(v, 0.f);
}

// ---------------- launch ----------------
extern "C" void kernel_launch(void* const* d_in, const int* in_sizes, int n_in,
                              void* d_out, int out_size)
{
    const float* x  = (const float*)d_in[0];
    const float* w1 = (const float*)d_in[1];
    const float* w2 = (const float*)d_in[2];
    const float* wa = (const float*)d_in[3];
    const float* wb = (const float*)d_in[4];
    const float* wc = (const float*)d_in[5];
    const float* wd = (const float*)d_in[6];

    void *pF0, *pF1t, *pnx1, *pfps1, *pgi1, *pF1max, *pnx2, *pfps2, *pgi2, *pF2max;
    void *pAh, *pAl, *pG, *pWh, *pWl, *ppsum, *ppsq, *pscale, *pbias, *pctr;
    cudaGetSymbolAddress(&pF0, g_F0);       cudaGetSymbolAddress(&pF1t, g_F1t);
    cudaGetSymbolAddress(&pnx1, g_nx1);     cudaGetSymbolAddress(&pfps1, g_fps1);
    cudaGetSymbolAddress(&pgi1, g_gi1);     cudaGetSymbolAddress(&pF1max, g_F1max);
    cudaGetSymbolAddress(&pnx2, g_nx2);     cudaGetSymbolAddress(&pfps2, g_fps2);
    cudaGetSymbolAddress(&pgi2, g_gi2);     cudaGetSymbolAddress(&pF2max, g_F2max);
    cudaGetSymbolAddress(&pAh, g_Ah);       cudaGetSymbolAddress(&pAl, g_Al);
    cudaGetSymbolAddress(&pG, g_G);
    cudaGetSymbolAddress(&pWh, g_Wh);       cudaGetSymbolAddress(&pWl, g_Wl);
    cudaGetSymbolAddress(&ppsum, g_psum);   cudaGetSymbolAddress(&ppsq, g_psq);
    cudaGetSymbolAddress(&pscale, g_scale); cudaGetSymbolAddress(&pbias, g_bias);
    cudaGetSymbolAddress(&pctr, g_ctr);

    double* psum = (double*)ppsum;
    double* psq  = (double*)ppsq;
    float* scl = (float*)pscale;
    float* bia = (float*)pbias;
    __nv_bfloat16* Ah = (__nv_bfloat16*)pAh;
    __nv_bfloat16* Al = (__nv_bfloat16*)pAl;
    float* G = (float*)pG;
    __nv_bfloat16* Wh = (__nv_bfloat16*)pWh;
    __nv_bfloat16* Wl = (__nv_bfloat16*)pWl;
    int* ctr = (int*)pctr;
    float* nx1 = (float*)pnx1;
    float* nx2 = (float*)pnx2;

    cudaMemsetAsync(psum, 0, 6*NSLOT*CMAX*sizeof(double), 0);
    cudaMemsetAsync(psq,  0, 6*NSLOT*CMAX*sizeof(double), 0);
    cudaMemsetAsync(ctr,  0, 8*sizeof(int), 0);

    k_wsplit<<<640,256>>>(wa, wb, wc, wd, Wh, Wl);

    // conv1 + fps1 (fps blocks first)
    k_conv1fps<<<32 + 2048, 256>>>(x, w1, (float*)pF0, psum, psq, ctr + 0, scl, bia,
                                   (int*)pfps1, nx1);
    // conv2 + ball1 + fps2 (fps2 first, then ball, then conv)
    k_conv2ball<<<32 + 2048 + 1024, 256>>>((const float*)pF0, w2, scl, bia,
                                      (float*)pF1t, psum + NSLOT*CMAX, psq + NSLOT*CMAX,
                                      ctr + 1, scl + CMAX, bia + CMAX,
                                      x, nx1, (int*)pgi1, (int*)pfps2, nx2);
    // gather1 standalone
    k_gather1<<<BB*S1, 256>>>((const float*)pF1t, scl + CMAX, bia + CMAX,
                              (const int*)pgi1, (const int*)pfps1, Ah, Al);
    // ball2
    k_ball2<<<BB*S2/8, 256>>>(nx1, nx2, (int*)pgi2);

    // sg1 GEMMs
    k_mma<128,128,true,false,true><<<dim3(NT1/128,1), 256>>>(Wh + 0, Wl + 0,
        nullptr, Ah, Al, nullptr, nullptr,
        G, nullptr, psum + 2*NSLOT*CMAX, psq + 2*NSLOT*CMAX,
        ctr + 2, NT1/128, 1.0/((double)NT1), scl + 2*CMAX, bia + 2*CMAX);
    k_mma<128,128,false,true,false><<<dim3(NT1/128,1), 256>>>(Wh + 16384, Wl + 16384,
        G, nullptr, nullptr, scl + 2*CMAX, bia + 2*CMAX,
        nullptr, (float*)pF1max, psum + 3*NSLOT*CMAX, psq + 3*NSLOT*CMAX,
        ctr + 3, NT1/128, 1.0/((double)NT1), scl + 3*CMAX, bia + 3*CMAX);

    // gather2
    k_gather2<<<BB*S2, 256>>>((const float*)pF1max, scl + 3*CMAX, bia + 3*CMAX,
                              (const int*)pgi2, (const int*)pfps2, Ah, Al);

    // sg2 GEMMs
    k_mma<256,256,true,false,true><<<dim3(NT2/128,2), 256>>>(Wh + 32768, Wl + 32768,
        nullptr, Ah, Al, nullptr, nullptr,
        G, nullptr, psum + 4*NSLOT*CMAX, psq + 4*NSLOT*CMAX,
        ctr + 4, (NT2/128)*2, 1.0/((double)NT2), scl + 4*CMAX, bia + 4*CMAX);
    k_mma<256,256,false,true,false><<<dim3(NT2/128,2), 256>>>(Wh + 98304, Wl + 98304,
        G, nullptr, nullptr, scl + 4*CMAX, bia + 4*CMAX,
        nullptr, (float*)pF2max, psum + 5*NSLOT*CMAX, psq + 5*NSLOT*CMAX,
        ctr + 5, (NT2/128)*2, 1.0/((double)NT2), scl + 5*CMAX, bia + 5*CMAX);

    // outputs
    cudaMemcpyAsync(d_out, pnx2, (size_t)BB*S2*3*sizeof(float), cudaMemcpyDeviceToDevice, 0);
    k_out_f2<<<(BB*256*256)/256, 256>>>((const float*)pF2max, scl + 5*CMAX, bia + 5*CMAX, (float*)d_out);
}